// round 6
// baseline (speedup 1.0000x reference)
#include <cuda_runtime.h>
#include <math.h>

#define NB 8
#define NGT 100
#define NC 80
#define T_TOTAL 13343

// Box-independent per-cell negative-focal sum (f64), computed once.
__device__ double g_sneg[NB * T_TOTAL];

__device__ __forceinline__ float neg_term(float v) {
    float cp = fminf(fmaxf(v, 1e-6f), 1.0f - 1e-6f);
    return (0.75f * (cp * cp)) * (-logf(1.0f - cp));
}

// ---------------------------------------------------------------------------
// Kernel 1: warp per (b,t) cell. 80 classes = lane, lane+32, lane+64(<16).
// Fully coalesced 128B lines; 3 independent loads in flight; f64 reduce.
// ---------------------------------------------------------------------------
__global__ __launch_bounds__(256) void sneg_kernel(const float* __restrict__ cls) {
    int cell = (blockIdx.x * blockDim.x + threadIdx.x) >> 5;
    int lane = threadIdx.x & 31;
    if (cell >= NB * T_TOTAL) return;
    const float* p = cls + (size_t)cell * NC;

    float a = p[lane];
    float b = p[lane + 32];
    float c = (lane < 16) ? p[lane + 64] : 0.0f;   // predicated, stays in-bounds

    double s = (double)neg_term(a) + (double)neg_term(b);
    if (lane < 16) s += (double)neg_term(c);

    #pragma unroll
    for (int o = 16; o; o >>= 1) s += __shfl_down_sync(0xffffffffu, s, o);
    if (lane == 0) g_sneg[cell] = s;
}

// ---------------------------------------------------------------------------
// Kernel 2: one block per (batch, gt-box); warp l owns FPN level l.
// Per masked cell: s_neg (8B) + cp[label] (4B) + regr (float4) + 3 logf.
// cnt <= 81 -> <= 3 iterations per lane. f64 accumulate; numpy argmin fold.
// ---------------------------------------------------------------------------
__global__ __launch_bounds__(160) void select_kernel(
        const float* __restrict__ cls,
        const float4* __restrict__ regr4,
        const float* __restrict__ gt,
        float* __restrict__ out) {
    const int   fdim_[5] = {100, 50, 25, 13, 7};
    const int   ls_[5]   = {0, 10000, 12500, 13125, 13294};
    const float st_[5]   = {8.f, 16.f, 32.f, 64.f, 128.f};

    int bn   = blockIdx.x;                 // b*100 + n
    int b    = bn / NGT;
    int tid  = threadIdx.x;
    int l    = tid >> 5;                   // warp = level
    int lane = tid & 31;

    __shared__ float  sbox[5];
    __shared__ double lvl[5];

    if (tid < 5) sbox[tid] = gt[(size_t)bn * 5 + tid];
    __syncthreads();

    float b0 = sbox[0], b1 = sbox[1], b2 = sbox[2], b3 = sbox[3];
    int   label = (int)sbox[4];
    if (!((fabsf(b0) + fabsf(b1) + fabsf(b2) + fabsf(b3)) > 0.0f)) {
        if (tid == 0) out[bn] = -1.0f;
        return;
    }

    const float*  clsb = cls   + (size_t)b * T_TOTAL * NC;
    const float4* regb = regr4 + (size_t)b * T_TOTAL;
    const double* snb  = g_sneg + (size_t)b * T_TOTAL;

    {
        float stride = st_[l];
        int   fw = fdim_[l], ls = ls_[l];

        // center-sampling rectangle: exact f32 replica of the reference
        float pb0 = b0 / stride, pb1 = b1 / stride;
        float pb2 = b2 / stride, pb3 = b3 / stride;
        float cx = (pb0 + pb2) * 0.5f, cy = (pb1 + pb3) * 0.5f;
        float hw = ((pb2 - pb0) * 0.2f) * 0.5f;
        float hh = ((pb3 - pb1) * 0.2f) * 0.5f;
        int x1 = (int)fminf(fmaxf(floorf(cx - hw), 0.0f), (float)(fw - 1));
        int y1 = (int)fminf(fmaxf(floorf(cy - hh), 0.0f), (float)(fw - 1));
        int x2 = min(max((int)ceilf(cx + hw), x1 + 1), fw);
        int y2 = min(max((int)ceilf(cy + hh), y1 + 1), fw);
        int nx  = x2 - x1;
        int cnt = nx * (y2 - y1);

        double s = 0.0;
        for (int cell = lane; cell < cnt; cell += 32) {
            int x = x1 + cell % nx;
            int y = y1 + cell / nx;
            int t = ls + y * fw + x;

            double sneg = snb[t];
            float  cpl  = clsb[(size_t)t * NC + label];
            float4 r    = regb[t];

            float cp = fminf(fmaxf(cpl, 1e-6f), 1.0f - 1e-6f);
            float om = 1.0f - cp;
            float neg_lab = (0.75f * (cp * cp)) * (-logf(om));
            float pos_lab = (0.25f * (om * om)) * (-logf(cp));

            float sx = ((float)x + 0.5f) * stride;
            float sy = ((float)y + 0.5f) * stride;
            float tl = (sx - b0) * 0.25f, tt = (sy - b1) * 0.25f;
            float tr = (b2 - sx) * 0.25f, tb = (b3 - sy) * 0.25f;
            float t_area = (tl + tr) * (tt + tb);
            float p_area = (r.x + r.z) * (r.y + r.w);
            float wi = fminf(r.x, tl) + fminf(r.z, tr);
            float hi = fminf(r.y, tt) + fminf(r.w, tb);
            float ai = wi * hi;
            float un = t_area + p_area - ai;
            float iou = -logf((ai + 1.0f) / (un + 1.0f));  // NaN propagates

            s += sneg - (double)neg_lab + (double)pos_lab + (double)iou;
        }

        #pragma unroll
        for (int o = 16; o; o >>= 1) s += __shfl_down_sync(0xffffffffu, s, o);
        if (lane == 0) lvl[l] = s / (double)cnt;
    }
    __syncthreads();

    if (tid == 0) {
        // numpy/jax argmin fold: pick if v<best, or v is NaN and best isn't.
        int    best = 0;
        double bv   = lvl[0];
        #pragma unroll
        for (int k = 1; k < 5; k++) {
            double v = lvl[k];
            if ((v < bv) || ((v != v) && (bv == bv))) { bv = v; best = k; }
        }
        out[bn] = (float)best;
    }
}

extern "C" void kernel_launch(void* const* d_in, const int* in_sizes, int n_in,
                              void* d_out, int out_size) {
    const float* cls  = (const float*)d_in[0];   // (8, 13343, 80) f32
    const float* regr = (const float*)d_in[1];   // (8, 13343, 4)  f32
    // d_in[2] = feature_shapes (compile-time constants, unused)
    const float* gt   = (const float*)d_in[3];   // (8, 100, 5)    f32
    float* out = (float*)d_out;                  // (8, 100)       f32

    // Kernel 1: 106744 cells, warp per cell, 8 warps/block.
    int ncells  = NB * T_TOTAL;
    int nblocks = (ncells + 7) / 8;
    sneg_kernel<<<nblocks, 256>>>(cls);

    // Kernel 2: block per (batch, box), warp per level.
    select_kernel<<<NB * NGT, 160>>>(cls, (const float4*)regr, gt, out);
}

// round 7
// speedup vs baseline: 3.7302x; 3.7302x over previous
#include <cuda_runtime.h>
#include <math.h>

#define NB 8
#define NGT 100
#define NC 80
#define T_TOTAL 13343

// Box-independent per-cell negative-focal sum, f32 (error ~1e-5 << level gaps).
__device__ float g_sneg[NB * T_TOTAL];

__device__ __forceinline__ float neg_term(float v) {
    float cp = fminf(fmaxf(v, 1e-6f), 1.0f - 1e-6f);
    return (0.75f * (cp * cp)) * (-__logf(1.0f - cp));
}

// two-sum compensated add (adds only -> no FMA-contraction hazard; NaN propagates)
__device__ __forceinline__ void df_add(float& hi, float& lo, float v) {
    float s   = hi + v;
    float bp  = s - hi;
    float err = (hi - (s - bp)) + (v - bp);
    hi = s; lo += err;
}

// ---------------------------------------------------------------------------
// Kernel 1: warp per (b,t) cell, pure f32 (NO FP64 in the bulk pass).
// Classes: lane, lane+32, lane+64(<16); coalesced 128B lines; f32 shuffle tree.
// ---------------------------------------------------------------------------
__global__ __launch_bounds__(256) void sneg_kernel(const float* __restrict__ cls) {
    int cell = (blockIdx.x * 256 + threadIdx.x) >> 5;
    int lane = threadIdx.x & 31;
    if (cell >= NB * T_TOTAL) return;
    const float* p = cls + (size_t)cell * NC;

    float a = p[lane];
    float b = p[lane + 32];
    float c = (lane < 16) ? p[lane + 64] : 0.0f;

    float s = neg_term(a) + neg_term(b);
    if (lane < 16) s += neg_term(c);

    #pragma unroll
    for (int o = 16; o; o >>= 1) s += __shfl_down_sync(0xffffffffu, s, o);
    if (lane == 0) g_sneg[cell] = s;
}

// ---------------------------------------------------------------------------
// Kernel 2: block per (batch, gt-box), warp l = FPN level l.
// Per masked cell: sneg(f32) + cp[label] + regr float4 + 2 logf.
// Double-float accumulation (f32 pipes); FP64 only in the 3-op epilogue.
// ---------------------------------------------------------------------------
__global__ __launch_bounds__(160) void select_kernel(
        const float* __restrict__ cls,
        const float4* __restrict__ regr4,
        const float* __restrict__ gt,
        float* __restrict__ out) {
    const int   fdim_[5] = {100, 50, 25, 13, 7};
    const int   ls_[5]   = {0, 10000, 12500, 13125, 13294};
    const float st_[5]   = {8.f, 16.f, 32.f, 64.f, 128.f};

    int bn   = blockIdx.x;                 // b*100 + n
    int b    = bn / NGT;
    int tid  = threadIdx.x;
    int l    = tid >> 5;                   // warp = level
    int lane = tid & 31;

    __shared__ float  sbox[5];
    __shared__ double lvl[5];

    if (tid < 5) sbox[tid] = gt[(size_t)bn * 5 + tid];
    __syncthreads();

    float b0 = sbox[0], b1 = sbox[1], b2 = sbox[2], b3 = sbox[3];
    int   label = (int)sbox[4];
    if (!((fabsf(b0) + fabsf(b1) + fabsf(b2) + fabsf(b3)) > 0.0f)) {
        if (tid == 0) out[bn] = -1.0f;
        return;
    }

    const float*  clsb = cls   + (size_t)b * T_TOTAL * NC;
    const float4* regb = regr4 + (size_t)b * T_TOTAL;
    const float*  snb  = g_sneg + (size_t)b * T_TOTAL;

    {
        float stride = st_[l];
        int   fw = fdim_[l], ls = ls_[l];

        // center-sampling rectangle: exact f32 replica of the reference
        float pb0 = b0 / stride, pb1 = b1 / stride;
        float pb2 = b2 / stride, pb3 = b3 / stride;
        float cx = (pb0 + pb2) * 0.5f, cy = (pb1 + pb3) * 0.5f;
        float hw = ((pb2 - pb0) * 0.2f) * 0.5f;
        float hh = ((pb3 - pb1) * 0.2f) * 0.5f;
        int x1 = (int)fminf(fmaxf(floorf(cx - hw), 0.0f), (float)(fw - 1));
        int y1 = (int)fminf(fmaxf(floorf(cy - hh), 0.0f), (float)(fw - 1));
        int x2 = min(max((int)ceilf(cx + hw), x1 + 1), fw);
        int y2 = min(max((int)ceilf(cy + hh), y1 + 1), fw);
        int nx  = x2 - x1;
        int cnt = nx * (y2 - y1);

        float shi = 0.0f, slo = 0.0f;
        for (int cell = lane; cell < cnt; cell += 32) {
            int x = x1 + cell % nx;
            int y = y1 + cell / nx;
            int t = ls + y * fw + x;

            float  sneg = snb[t];
            float  cpl  = clsb[(size_t)t * NC + label];
            float4 r    = regb[t];

            float cp = fminf(fmaxf(cpl, 1e-6f), 1.0f - 1e-6f);
            float om = 1.0f - cp;
            float neg_lab = (0.75f * (cp * cp)) * (-logf(om));
            float pos_lab = (0.25f * (om * om)) * (-logf(cp));

            float sx = ((float)x + 0.5f) * stride;
            float sy = ((float)y + 0.5f) * stride;
            float tl = (sx - b0) * 0.25f, tt = (sy - b1) * 0.25f;
            float tr = (b2 - sx) * 0.25f, tb = (b3 - sy) * 0.25f;
            float t_area = (tl + tr) * (tt + tb);
            float p_area = (r.x + r.z) * (r.y + r.w);
            float wi = fminf(r.x, tl) + fminf(r.z, tr);
            float hi = fminf(r.y, tt) + fminf(r.w, tb);
            float ai = wi * hi;
            float un = t_area + p_area - ai;
            float iou = -logf((ai + 1.0f) / (un + 1.0f));  // NaN propagates

            df_add(shi, slo, sneg - neg_lab + pos_lab);
            df_add(shi, slo, iou);
        }

        // warp reduction in double-float
        #pragma unroll
        for (int o = 16; o; o >>= 1) {
            float ohi = __shfl_down_sync(0xffffffffu, shi, o);
            float olo = __shfl_down_sync(0xffffffffu, slo, o);
            df_add(shi, slo, ohi);
            slo += olo;
        }
        if (lane == 0) lvl[l] = ((double)shi + (double)slo) / (double)cnt;
    }
    __syncthreads();

    if (tid == 0) {
        // numpy/jax argmin fold: pick if v<best, or v is NaN and best isn't.
        int    best = 0;
        double bv   = lvl[0];
        #pragma unroll
        for (int k = 1; k < 5; k++) {
            double v = lvl[k];
            if ((v < bv) || ((v != v) && (bv == bv))) { bv = v; best = k; }
        }
        out[bn] = (float)best;
    }
}

extern "C" void kernel_launch(void* const* d_in, const int* in_sizes, int n_in,
                              void* d_out, int out_size) {
    const float* cls  = (const float*)d_in[0];   // (8, 13343, 80) f32
    const float* regr = (const float*)d_in[1];   // (8, 13343, 4)  f32
    // d_in[2] = feature_shapes (compile-time constants, unused)
    const float* gt   = (const float*)d_in[3];   // (8, 100, 5)    f32
    float* out = (float*)d_out;                  // (8, 100)       f32

    // Kernel 1: 106744 cells, warp per cell, 8 warps/block.
    int ncells  = NB * T_TOTAL;
    int nblocks = (ncells + 7) / 8;
    sneg_kernel<<<nblocks, 256>>>(cls);

    // Kernel 2: block per (batch, box), warp per level.
    select_kernel<<<NB * NGT, 160>>>(cls, (const float4*)regr, gt, out);
}

// round 8
// speedup vs baseline: 3.7359x; 1.0015x over previous
#include <cuda_runtime.h>
#include <math.h>

#define NB 8
#define NGT 100
#define NC 80
#define T_TOTAL 13343
#define NCELLS (NB * T_TOTAL)          // 106744
#define QPC (NC / 4)                   // 20 float4 quads per cell
#define TOTALQ ((long long)NCELLS * QPC)

#define K1_T 320                       // threads per k1 block
#define K1_CELLS (K1_T / QPC)          // 16 cells per k1 block

// Box-independent per-cell negative-focal sum, f32.
__device__ float g_sneg[NCELLS];

__device__ __forceinline__ float neg_term(float v) {
    float cp = fminf(fmaxf(v, 1e-6f), 1.0f - 1e-6f);
    return (0.75f * (cp * cp)) * (-__logf(1.0f - cp));
}

// ---------------------------------------------------------------------------
// Kernel 1: one float4 per thread over the flat (cells*80) tensor; per-cell
// segmented reduce through smem in a fixed (deterministic) order.
// ---------------------------------------------------------------------------
__global__ __launch_bounds__(K1_T) void sneg_kernel(const float4* __restrict__ cls4) {
    __shared__ float psum[K1_T];
    int tid = threadIdx.x;
    long long q = (long long)blockIdx.x * K1_T + tid;

    float s = 0.0f;
    if (q < TOTALQ) {
        float4 v = cls4[q];
        s = (neg_term(v.x) + neg_term(v.y)) + (neg_term(v.z) + neg_term(v.w));
    }
    psum[tid] = s;
    __syncthreads();

    if (tid < K1_CELLS) {
        int cell = blockIdx.x * K1_CELLS + tid;
        if (cell < NCELLS) {
            float acc = 0.0f;
            #pragma unroll
            for (int j = 0; j < QPC; j++) acc += psum[tid * QPC + j];
            g_sneg[cell] = acc;
        }
    }
}

// ---------------------------------------------------------------------------
// Kernel 2: block per (batch, gt-box), ONE masked cell per thread (total
// masked cells over all 5 levels <= ~135 < 160). Warp l then reduces level
// l's segment in f64. No serial per-cell loop anywhere.
// ---------------------------------------------------------------------------
__global__ __launch_bounds__(160) void select_kernel(
        const float* __restrict__ cls,
        const float4* __restrict__ regr4,
        const float* __restrict__ gt,
        float* __restrict__ out) {
    const int   fdim_[5] = {100, 50, 25, 13, 7};
    const int   ls_[5]   = {0, 10000, 12500, 13125, 13294};
    const float st_[5]   = {8.f, 16.f, 32.f, 64.f, 128.f};

    int bn   = blockIdx.x;                 // b*100 + n
    int b    = bn / NGT;
    int tid  = threadIdx.x;
    int lane = tid & 31;
    int wid  = tid >> 5;

    __shared__ float  sval[160];
    __shared__ double lvl[5];

    // every thread loads the 5 box floats (same address -> broadcast)
    const float* gbox = gt + (size_t)bn * 5;
    float b0 = __ldg(gbox + 0), b1 = __ldg(gbox + 1);
    float b2 = __ldg(gbox + 2), b3 = __ldg(gbox + 3);
    int   label = (int)__ldg(gbox + 4);

    if (!((fabsf(b0) + fabsf(b1) + fabsf(b2) + fabsf(b3)) > 0.0f)) {
        if (tid == 0) out[bn] = -1.0f;
        return;
    }

    const float*  clsb = cls    + (size_t)b * T_TOTAL * NC;
    const float4* regb = regr4  + (size_t)b * T_TOTAL;
    const float*  snb  = g_sneg + (size_t)b * T_TOTAL;

    // redundantly compute all 5 rects (exact f32 replica of the reference)
    int rx1[5], ry1[5], rnx[5], rcnt[5];
    #pragma unroll
    for (int k = 0; k < 5; k++) {
        float stride = st_[k];
        int   fw = fdim_[k];
        float pb0 = b0 / stride, pb1 = b1 / stride;
        float pb2 = b2 / stride, pb3 = b3 / stride;
        float cx = (pb0 + pb2) * 0.5f, cy = (pb1 + pb3) * 0.5f;
        float hw = ((pb2 - pb0) * 0.2f) * 0.5f;
        float hh = ((pb3 - pb1) * 0.2f) * 0.5f;
        int x1 = (int)fminf(fmaxf(floorf(cx - hw), 0.0f), (float)(fw - 1));
        int y1 = (int)fminf(fmaxf(floorf(cy - hh), 0.0f), (float)(fw - 1));
        int x2 = min(max((int)ceilf(cx + hw), x1 + 1), fw);
        int y2 = min(max((int)ceilf(cy + hh), y1 + 1), fw);
        rx1[k] = x1; ry1[k] = y1;
        rnx[k] = x2 - x1;
        rcnt[k] = (x2 - x1) * (y2 - y1);
    }

    // map tid -> (level l, level-local cell c)
    int l = -1, c = tid;
    #pragma unroll
    for (int k = 0; k < 5; k++) {
        if (l < 0) { if (c < rcnt[k]) l = k; else c -= rcnt[k]; }
    }

    if (l >= 0) {
        int nx = rnx[l];
        int x  = rx1[l] + c % nx;
        int y  = ry1[l] + c / nx;
        int t  = ls_[l] + y * fdim_[l] + x;
        float stride = st_[l];

        float  sneg = snb[t];
        float  cpl  = clsb[(size_t)t * NC + label];
        float4 r    = regb[t];

        float cp = fminf(fmaxf(cpl, 1e-6f), 1.0f - 1e-6f);
        float om = 1.0f - cp;
        float neg_lab = (0.75f * (cp * cp)) * (-logf(om));
        float pos_lab = (0.25f * (om * om)) * (-logf(cp));

        float sx = ((float)x + 0.5f) * stride;
        float sy = ((float)y + 0.5f) * stride;
        float tl = (sx - b0) * 0.25f, tt = (sy - b1) * 0.25f;
        float tr = (b2 - sx) * 0.25f, tb = (b3 - sy) * 0.25f;
        float t_area = (tl + tr) * (tt + tb);
        float p_area = (r.x + r.z) * (r.y + r.w);
        float wi = fminf(r.x, tl) + fminf(r.z, tr);
        float hi = fminf(r.y, tt) + fminf(r.w, tb);
        float ai = wi * hi;
        float un = t_area + p_area - ai;
        float iou = -logf((ai + 1.0f) / (un + 1.0f));  // NaN propagates

        sval[tid] = (sneg - neg_lab + pos_lab) + iou;
    }
    __syncthreads();

    // warp w reduces level w's segment in f64 (fixed order -> deterministic)
    if (wid < 5) {
        int pre = 0;
        #pragma unroll
        for (int k = 0; k < 5; k++) if (k < wid) pre += rcnt[k];
        int cnt = rcnt[wid];
        double s = 0.0;
        for (int i = lane; i < cnt; i += 32) s += (double)sval[pre + i];
        #pragma unroll
        for (int o = 16; o; o >>= 1) s += __shfl_down_sync(0xffffffffu, s, o);
        if (lane == 0) lvl[wid] = s / (double)cnt;
    }
    __syncthreads();

    if (tid == 0) {
        // numpy/jax argmin fold: pick if v<best, or v is NaN and best isn't.
        int    best = 0;
        double bv   = lvl[0];
        #pragma unroll
        for (int k = 1; k < 5; k++) {
            double v = lvl[k];
            if ((v < bv) || ((v != v) && (bv == bv))) { bv = v; best = k; }
        }
        out[bn] = (float)best;
    }
}

extern "C" void kernel_launch(void* const* d_in, const int* in_sizes, int n_in,
                              void* d_out, int out_size) {
    const float* cls  = (const float*)d_in[0];   // (8, 13343, 80) f32
    const float* regr = (const float*)d_in[1];   // (8, 13343, 4)  f32
    // d_in[2] = feature_shapes (compile-time constants, unused)
    const float* gt   = (const float*)d_in[3];   // (8, 100, 5)    f32
    float* out = (float*)d_out;                  // (8, 100)       f32

    // Kernel 1: flat float4 pass, 16 cells per 320-thread block.
    int nblocks = (int)((TOTALQ + K1_T - 1) / K1_T);   // 6672
    sneg_kernel<<<nblocks, K1_T>>>((const float4*)cls);

    // Kernel 2: block per (batch, box), one masked cell per thread.
    select_kernel<<<NB * NGT, 160>>>(cls, (const float4*)regr, gt, out);
}